// round 6
// baseline (speedup 1.0000x reference)
#include <cuda_runtime.h>

#define NN 100000
#define EE 1600000

// ---------------- scratch (static device globals; no allocation) ------------
__device__ float  g_h[NN * 128];       // node features, updated in place
__device__ float2 g_hblk2[NN * 32];    // relu(LN(half)): lane -> (ch, ch+32)
__device__ float2 g_agg2[NN * 32];     // softmax aggregation
__device__ int    g_cnt[NN];           // zero-init; re-zeroed by k_scan each run
__device__ int    g_off[NN + 1];
__device__ int    g_cur[NN];
__device__ int    g_srcp[EE];          // src permuted by dst
__device__ float  g_eap[EE * 8];       // edge_attr permuted by dst
__device__ float  g_wc[4 * 8 * 64];    // folded W_ee @ We per block
__device__ float  g_bc[4 * 64];        // folded bias per block

// ---------------- histogram ---------------------------------------------------
__global__ void k_hist(const int* __restrict__ dst) {
    int i = blockIdx.x * blockDim.x + threadIdx.x;
    if (i < EE) atomicAdd(&g_cnt[dst[i]], 1);
}

// ------- scan: 4 elems/thread, 25 serial chunks; re-zeroes g_cnt ------------
__global__ void k_scan() {
    __shared__ int wsum[32];
    __shared__ int s_carry;
    int tid = threadIdx.x, lane = tid & 31, wid = tid >> 5;
    if (tid == 0) s_carry = 0;
    __syncthreads();
    for (int base = 0; base < NN; base += 4096) {
        int i0 = base + tid * 4;
        int v[4];
        #pragma unroll
        for (int u = 0; u < 4; u++) {
            int i = i0 + u;
            v[u] = (i < NN) ? g_cnt[i] : 0;
            if (i < NN) g_cnt[i] = 0;
        }
        int tsum = v[0] + v[1] + v[2] + v[3];
        int x = tsum;
        #pragma unroll
        for (int d = 1; d < 32; d <<= 1) {
            int t = __shfl_up_sync(0xffffffffu, x, d);
            if (lane >= d) x += t;
        }
        if (lane == 31) wsum[wid] = x;
        __syncthreads();
        if (wid == 0) {
            int w = wsum[lane];
            #pragma unroll
            for (int d = 1; d < 32; d <<= 1) {
                int t = __shfl_up_sync(0xffffffffu, w, d);
                if (lane >= d) w += t;
            }
            wsum[lane] = w;
        }
        __syncthreads();
        int carry = s_carry;
        int run = x - tsum + ((wid > 0) ? wsum[wid - 1] : 0) + carry;
        #pragma unroll
        for (int u = 0; u < 4; u++) {
            int i = i0 + u;
            if (i < NN) { g_off[i] = run; g_cur[i] = run; }
            run += v[u];
        }
        __syncthreads();
        if (tid == 0) s_carry = carry + wsum[31];
        __syncthreads();
    }
    if (tid == 0) g_off[NN] = s_carry;
}

// ---------------- scatter edges by dst ---------------------------------------
__global__ void k_scatter(const int* __restrict__ src, const int* __restrict__ dst,
                          const float4* __restrict__ ea) {
    int i = blockIdx.x * blockDim.x + threadIdx.x;
    if (i < EE) {
        int d = dst[i];
        int pos = atomicAdd(&g_cur[d], 1);
        g_srcp[pos] = src[i];
        float4* o = (float4*)g_eap;
        o[pos * 2]     = ea[i * 2];
        o[pos * 2 + 1] = ea[i * 2 + 1];
    }
}

// ------- fold ee@We into 8x64 per block: warp per output element ------------
__global__ void k_wc(const float* __restrict__ Wee, const float* __restrict__ bee,
                     const float* __restrict__ We, const float* __restrict__ be) {
    int lane = threadIdx.x & 31;
    int w = blockIdx.x * 8 + (threadIdx.x >> 5);
    if (w < 2048) {
        int b = w >> 9, k = (w >> 6) & 7, c = w & 63;
        float s = 0.f;
        for (int j = lane; j < 128; j += 32)
            s += Wee[k * 128 + j] * We[(b * 128 + j) * 64 + c];
        #pragma unroll
        for (int d = 16; d > 0; d >>= 1) s += __shfl_xor_sync(0xffffffffu, s, d);
        if (lane == 0) g_wc[w] = s;
    } else if (w < 2304) {
        int idx = w - 2048;
        int b = idx >> 6, c = idx & 63;
        float s = 0.f;
        for (int j = lane; j < 128; j += 32)
            s += bee[j] * We[(b * 128 + j) * 64 + c];
        #pragma unroll
        for (int d = 16; d > 0; d >>= 1) s += __shfl_xor_sync(0xffffffffu, s, d);
        if (lane == 0) g_bc[idx] = be[idx] + s;
    }
}

// ---------------- node encoder (+ fused LN/relu for block 0) ----------------
__global__ void k_encode(const float* __restrict__ x, const int* __restrict__ nidx,
                         const float* __restrict__ nodef,
                         const float* __restrict__ Woh, const float* __restrict__ boh,
                         const float* __restrict__ Wne, const float* __restrict__ bne,
                         const float* __restrict__ ln0g, const float* __restrict__ ln0b) {
    __shared__ float s_woh[64], s_boh[8], s_wne[2048], s_bne[128];
    for (int i = threadIdx.x; i < 64; i += blockDim.x) s_woh[i] = Woh[i];
    for (int i = threadIdx.x; i < 8; i += blockDim.x) s_boh[i] = boh[i];
    for (int i = threadIdx.x; i < 2048; i += blockDim.x) s_wne[i] = Wne[i];
    for (int i = threadIdx.x; i < 128; i += blockDim.x) s_bne[i] = bne[i];
    __syncthreads();
    int lane = threadIdx.x & 31;
    int warp = blockIdx.x * (blockDim.x >> 5) + (threadIdx.x >> 5);
    int nw = gridDim.x * (blockDim.x >> 5);
    for (int n = warp; n < NN; n += nw) {
        int s = nidx[n];
        float4 a  = *(const float4*)(nodef + s * 8);
        float4 b4 = *(const float4*)(nodef + s * 8 + 4);
        float nf1[8] = {a.x, a.y, a.z, a.w, b4.x, b4.y, b4.z, b4.w};
        float4 xa = *(const float4*)(x + n * 8);
        float4 xb = *(const float4*)(x + n * 8 + 4);
        float xv[8] = {xa.x, xa.y, xa.z, xa.w, xb.x, xb.y, xb.z, xb.w};
        float nf2[8];
        #pragma unroll
        for (int j = 0; j < 8; j++) {
            float t = s_boh[j];
            #pragma unroll
            for (int i = 0; i < 8; i++) t += xv[i] * s_woh[i * 8 + j];
            nf2[j] = t;
        }
        float acc[4];
        #pragma unroll
        for (int cc = 0; cc < 4; cc++) {
            int c = lane + cc * 32;
            float t = s_bne[c];
            #pragma unroll
            for (int k = 0; k < 8; k++) t += nf1[k] * s_wne[k * 128 + c];
            #pragma unroll
            for (int k = 0; k < 8; k++) t += nf2[k] * s_wne[(8 + k) * 128 + c];
            g_h[n * 128 + c] = t;
            acc[cc] = t;
        }
        float v0 = acc[2], v1 = acc[3];
        float su = v0 + v1, q = v0 * v0 + v1 * v1;
        #pragma unroll
        for (int d = 16; d > 0; d >>= 1) {
            su += __shfl_xor_sync(0xffffffffu, su, d);
            q  += __shfl_xor_sync(0xffffffffu, q, d);
        }
        float mu = su * (1.f / 64.f);
        float rs = rsqrtf(q * (1.f / 64.f) - mu * mu + 1e-5f);
        float r0 = fmaxf((v0 - mu) * rs * ln0g[lane] + ln0b[lane], 0.f);
        float r1 = fmaxf((v1 - mu) * rs * ln0g[lane + 32] + ln0b[lane + 32], 0.f);
        g_hblk2[n * 32 + lane] = make_float2(r0, r1);
    }
}

// ------- softmax aggregation: 4 warps per node, 2 nodes per block -----------
// Unshifted softmax (exact: msg bounded, weights invariant to shift/+eps).
// d,n are plain sums -> edges split across 4 warps, combined in smem.
__global__ void __launch_bounds__(256) k_agg4(int bsel) {
    __shared__ float red[8][128];
    int tid = threadIdx.x;
    int lane = tid & 31, wid = tid >> 5;
    int local = wid >> 2, sub = wid & 3;
    int node = blockIdx.x * 2 + local;      // grid*2 == NN exactly
    const float* Wc = g_wc + bsel * 512;
    float wA[8], wB[8];
    #pragma unroll
    for (int k = 0; k < 8; k++) {
        wA[k] = __ldg(&Wc[k * 64 + lane]);
        wB[k] = __ldg(&Wc[k * 64 + lane + 32]);
    }
    float bc0 = __ldg(&g_bc[bsel * 64 + lane]);
    float bc1 = __ldg(&g_bc[bsel * 64 + lane + 32]);
    int e0 = __ldg(&g_off[node]), e1 = __ldg(&g_off[node + 1]);
    int per = (e1 - e0 + 3) >> 2;
    int cs = e0 + sub * per;
    int ce = min(cs + per, e1);
    float d0 = 0.f, d1 = 0.f, n0 = 0.f, n1 = 0.f;
    const float4* eap = (const float4*)g_eap;
    #pragma unroll 2
    for (int e = cs; e < ce; e++) {
        int s = __ldg(&g_srcp[e]);
        float2 hv = __ldg(&g_hblk2[s * 32 + lane]);
        float4 A = __ldg(&eap[e * 2]);
        float4 B = __ldg(&eap[e * 2 + 1]);
        float t0 = bc0 + hv.x, t1 = bc1 + hv.y;
        t0 = fmaf(A.x, wA[0], t0);  t1 = fmaf(A.x, wB[0], t1);
        t0 = fmaf(A.y, wA[1], t0);  t1 = fmaf(A.y, wB[1], t1);
        t0 = fmaf(A.z, wA[2], t0);  t1 = fmaf(A.z, wB[2], t1);
        t0 = fmaf(A.w, wA[3], t0);  t1 = fmaf(A.w, wB[3], t1);
        t0 = fmaf(B.x, wA[4], t0);  t1 = fmaf(B.x, wB[4], t1);
        t0 = fmaf(B.y, wA[5], t0);  t1 = fmaf(B.y, wB[5], t1);
        t0 = fmaf(B.z, wA[6], t0);  t1 = fmaf(B.z, wB[6], t1);
        t0 = fmaf(B.w, wA[7], t0);  t1 = fmaf(B.w, wB[7], t1);
        float v0 = fmaxf(t0, 0.f);
        float v1 = fmaxf(t1, 0.f);
        float ex0 = __expf(v0);
        float ex1 = __expf(v1);
        d0 += ex0;  n0 = fmaf(v0, ex0, n0);
        d1 += ex1;  n1 = fmaf(v1, ex1, n1);
    }
    red[wid][lane]      = d0;
    red[wid][lane + 32] = d1;
    red[wid][lane + 64] = n0;
    red[wid][lane + 96] = n1;
    __syncthreads();
    if (sub == 0) {
        int q0 = local * 4;
        float D0 = red[q0][lane]      + red[q0+1][lane]      + red[q0+2][lane]      + red[q0+3][lane];
        float D1 = red[q0][lane + 32] + red[q0+1][lane + 32] + red[q0+2][lane + 32] + red[q0+3][lane + 32];
        float N0 = red[q0][lane + 64] + red[q0+1][lane + 64] + red[q0+2][lane + 64] + red[q0+3][lane + 64];
        float N1 = red[q0][lane + 96] + red[q0+1][lane + 96] + red[q0+2][lane + 96] + red[q0+3][lane + 96];
        float a0 = (D0 > 0.f) ? (N0 / D0 + 1e-7f) : 0.f;
        float a1 = (D1 > 0.f) ? (N1 / D1 + 1e-7f) : 0.f;
        g_agg2[node * 32 + lane] = make_float2(a0, a1);
    }
}

// ---- per-block: y += (h_blk + agg) @ Wm + bm, fused next-block LN/relu -----
__global__ void k_mlp(int bsel, int outoff, const float* __restrict__ Wm,
                      const float* __restrict__ bm,
                      const float* __restrict__ ng, const float* __restrict__ nb) {
    __shared__ float wms[4096];
    const float* W = Wm + bsel * 4096;
    for (int i = threadIdx.x; i < 4096; i += blockDim.x) wms[i] = W[i];
    __syncthreads();
    int lane = threadIdx.x & 31;
    int warp = blockIdx.x * (blockDim.x >> 5) + (threadIdx.x >> 5);
    int nw = gridDim.x * (blockDim.x >> 5);
    float b0 = bm[bsel * 64 + lane], b1 = bm[bsel * 64 + lane + 32];
    float g0 = 0.f, g1 = 0.f, bb0 = 0.f, bb1 = 0.f;
    if (ng) { g0 = ng[lane]; g1 = ng[lane + 32]; bb0 = nb[lane]; bb1 = nb[lane + 32]; }
    for (int n = warp * 2; n < NN; n += nw * 2) {
        int n2 = n + 1;
        float2 hA = g_hblk2[n * 32 + lane],  aA = g_agg2[n * 32 + lane];
        float2 hB = g_hblk2[n2 * 32 + lane], aB = g_agg2[n2 * 32 + lane];
        float aA0 = hA.x + aA.x, aA1 = hA.y + aA.y;
        float aB0 = hB.x + aB.x, aB1 = hB.y + aB.y;
        float accA0 = b0, accA1 = b1, accB0 = b0, accB1 = b1;
        #pragma unroll
        for (int k = 0; k < 32; k++) {
            float w0 = wms[k * 64 + lane];
            float w1 = wms[k * 64 + lane + 32];
            float vA = __shfl_sync(0xffffffffu, aA0, k);
            float vB = __shfl_sync(0xffffffffu, aB0, k);
            accA0 = fmaf(vA, w0, accA0);  accA1 = fmaf(vA, w1, accA1);
            accB0 = fmaf(vB, w0, accB0);  accB1 = fmaf(vB, w1, accB1);
        }
        #pragma unroll
        for (int k = 0; k < 32; k++) {
            float w0 = wms[(k + 32) * 64 + lane];
            float w1 = wms[(k + 32) * 64 + lane + 32];
            float vA = __shfl_sync(0xffffffffu, aA1, k);
            float vB = __shfl_sync(0xffffffffu, aB1, k);
            accA0 = fmaf(vA, w0, accA0);  accA1 = fmaf(vA, w1, accA1);
            accB0 = fmaf(vB, w0, accB0);  accB1 = fmaf(vB, w1, accB1);
        }
        float* oA = g_h + n * 128 + outoff;
        float* oB = g_h + n2 * 128 + outoff;
        float nA0 = oA[lane] + accA0, nA1 = oA[lane + 32] + accA1;
        float nB0 = oB[lane] + accB0, nB1 = oB[lane + 32] + accB1;
        oA[lane] = nA0;  oA[lane + 32] = nA1;
        oB[lane] = nB0;  oB[lane + 32] = nB1;
        if (ng) {
            float sA = nA0 + nA1, qA = nA0 * nA0 + nA1 * nA1;
            float sB = nB0 + nB1, qB = nB0 * nB0 + nB1 * nB1;
            #pragma unroll
            for (int d = 16; d > 0; d >>= 1) {
                sA += __shfl_xor_sync(0xffffffffu, sA, d);
                qA += __shfl_xor_sync(0xffffffffu, qA, d);
                sB += __shfl_xor_sync(0xffffffffu, sB, d);
                qB += __shfl_xor_sync(0xffffffffu, qB, d);
            }
            float muA = sA * (1.f / 64.f), muB = sB * (1.f / 64.f);
            float rsA = rsqrtf(qA * (1.f / 64.f) - muA * muA + 1e-5f);
            float rsB = rsqrtf(qB * (1.f / 64.f) - muB * muB + 1e-5f);
            g_hblk2[n * 32 + lane] = make_float2(
                fmaxf((nA0 - muA) * rsA * g0 + bb0, 0.f),
                fmaxf((nA1 - muA) * rsA * g1 + bb1, 0.f));
            g_hblk2[n2 * 32 + lane] = make_float2(
                fmaxf((nB0 - muB) * rsB * g0 + bb0, 0.f),
                fmaxf((nB1 - muB) * rsB * g1 + bb1, 0.f));
        }
    }
}

// ---------------- final: out = relu(LN(h)) @ Wp + bp (56-col chunks) --------
__global__ void k_final(const float* __restrict__ lg, const float* __restrict__ lb,
                        const float* __restrict__ Wp, const float* __restrict__ bp,
                        float* __restrict__ out, int col0) {
    __shared__ float wps[128 * 56];
    for (int i = threadIdx.x; i < 128 * 56; i += blockDim.x) {
        int k = i / 56, c = i % 56;
        wps[i] = Wp[k * 112 + col0 + c];
    }
    __syncthreads();
    int lane = threadIdx.x & 31;
    int warp = blockIdx.x * (blockDim.x >> 5) + (threadIdx.x >> 5);
    int nw = gridDim.x * (blockDim.x >> 5);
    bool hasB = lane < 24;
    int cA = lane, cB = hasB ? lane + 32 : 0;
    float bpA = bp[col0 + cA];
    float bpB = hasB ? bp[col0 + lane + 32] : 0.f;
    float lgv[4], lbv[4];
    #pragma unroll
    for (int i = 0; i < 4; i++) { lgv[i] = lg[lane + i * 32]; lbv[i] = lb[lane + i * 32]; }
    for (int n = warp * 2; n < NN; n += nw * 2) {
        int n2 = n + 1;
        const float* hA = g_h + n * 128;
        const float* hB = g_h + n2 * 128;
        float xA[4], xB[4];
        #pragma unroll
        for (int i = 0; i < 4; i++) { xA[i] = hA[lane + i * 32]; xB[i] = hB[lane + i * 32]; }
        float sA = 0.f, qA = 0.f, sB = 0.f, qB = 0.f;
        #pragma unroll
        for (int i = 0; i < 4; i++) {
            sA += xA[i]; qA += xA[i] * xA[i];
            sB += xB[i]; qB += xB[i] * xB[i];
        }
        #pragma unroll
        for (int d = 16; d > 0; d >>= 1) {
            sA += __shfl_xor_sync(0xffffffffu, sA, d);
            qA += __shfl_xor_sync(0xffffffffu, qA, d);
            sB += __shfl_xor_sync(0xffffffffu, sB, d);
            qB += __shfl_xor_sync(0xffffffffu, qB, d);
        }
        float muA = sA * (1.f / 128.f), muB = sB * (1.f / 128.f);
        float rsA = rsqrtf(qA * (1.f / 128.f) - muA * muA + 1e-5f);
        float rsB = rsqrtf(qB * (1.f / 128.f) - muB * muB + 1e-5f);
        #pragma unroll
        for (int i = 0; i < 4; i++) {
            xA[i] = fmaxf((xA[i] - muA) * rsA * lgv[i] + lbv[i], 0.f);
            xB[i] = fmaxf((xB[i] - muB) * rsB * lgv[i] + lbv[i], 0.f);
        }
        float aA0 = bpA, aA1 = bpB, aB0 = bpA, aB1 = bpB;
        #pragma unroll
        for (int i = 0; i < 4; i++) {
            #pragma unroll
            for (int k = 0; k < 32; k++) {
                float w0 = wps[(k + i * 32) * 56 + cA];
                float w1 = wps[(k + i * 32) * 56 + cB];
                float vA = __shfl_sync(0xffffffffu, xA[i], k);
                float vB = __shfl_sync(0xffffffffu, xB[i], k);
                aA0 = fmaf(vA, w0, aA0);  aA1 = fmaf(vA, w1, aA1);
                aB0 = fmaf(vB, w0, aB0);  aB1 = fmaf(vB, w1, aB1);
            }
        }
        out[n * 112 + col0 + cA] = aA0;
        out[n2 * 112 + col0 + cA] = aB0;
        if (hasB) {
            out[n * 112 + col0 + lane + 32] = aA1;
            out[n2 * 112 + col0 + lane + 32] = aB1;
        }
    }
}

// ---------------- launch ----------------------------------------------------
extern "C" void kernel_launch(void* const* d_in, const int* in_sizes, int n_in,
                              void* d_out, int out_size) {
    const float* x     = (const float*)d_in[0];
    const int*   nidx  = (const int*)d_in[1];
    const int*   ei    = (const int*)d_in[2];
    const float* ea    = (const float*)d_in[3];
    const float* nodef = (const float*)d_in[4];
    const float* Woh   = (const float*)d_in[5];
    const float* boh   = (const float*)d_in[6];
    const float* Wne   = (const float*)d_in[7];
    const float* bne   = (const float*)d_in[8];
    const float* Wee   = (const float*)d_in[9];
    const float* bee   = (const float*)d_in[10];
    const float* lng   = (const float*)d_in[11];
    const float* lnb   = (const float*)d_in[12];
    const float* We    = (const float*)d_in[13];
    const float* be    = (const float*)d_in[14];
    const float* Wm    = (const float*)d_in[15];
    const float* bm    = (const float*)d_in[16];
    const float* lastg = (const float*)d_in[17];
    const float* lastb = (const float*)d_in[18];
    const float* Wp    = (const float*)d_in[19];
    const float* bp    = (const float*)d_in[20];
    float* out = (float*)d_out;

    const int* src = ei;
    const int* dst = ei + EE;

    k_hist<<<(EE + 255) / 256, 256>>>(dst);
    k_scan<<<1, 1024>>>();
    k_scatter<<<(EE + 255) / 256, 256>>>(src, dst, (const float4*)ea);
    k_wc<<<288, 256>>>(Wee, bee, We, be);
    k_encode<<<1184, 256>>>(x, nidx, nodef, Woh, boh, Wne, bne, lng, lnb);

    for (int b = 0; b < 4; b++) {
        int outoff = (b & 1) ? 64 : 0;
        const float* ng = (b < 3) ? (lng + (b + 1) * 64) : (const float*)0;
        const float* nbp = (b < 3) ? (lnb + (b + 1) * 64) : (const float*)0;
        k_agg4<<<NN / 2, 256>>>(b);
        k_mlp<<<1184, 256>>>(b, outoff, Wm, bm, ng, nbp);
    }

    k_final<<<1184, 256>>>(lastg, lastb, Wp, bp, out, 0);
    k_final<<<1184, 256>>>(lastg, lastb, Wp, bp, out, 56);
}

// round 7
// speedup vs baseline: 1.1676x; 1.1676x over previous
#include <cuda_runtime.h>

#define NN 100000
#define EE 1600000

// ---------------- scratch (static device globals; no allocation) ------------
__device__ float  g_h[NN * 128];       // node features, updated in place
__device__ float2 g_hblkA[NN * 32];    // ping-pong relu(LN(half)) buffers
__device__ float2 g_hblkB[NN * 32];
__device__ int    g_cnt[NN];           // zero-init; re-zeroed by k_scan each run
__device__ int    g_off[NN + 1];
__device__ int    g_cur[NN];
__device__ int    g_srcp[EE];          // src permuted by dst
__device__ float  g_eap[EE * 8];       // edge_attr permuted by dst
__device__ float  g_wc[4 * 8 * 64];    // folded W_ee @ We per block
__device__ float  g_bc[4 * 64];        // folded bias per block

// ---------------- histogram ---------------------------------------------------
__global__ void k_hist(const int* __restrict__ dst) {
    int i = blockIdx.x * blockDim.x + threadIdx.x;
    if (i < EE) atomicAdd(&g_cnt[dst[i]], 1);
}

// ------- scan: 4 elems/thread, 25 serial chunks; re-zeroes g_cnt ------------
__global__ void k_scan() {
    __shared__ int wsum[32];
    __shared__ int s_carry;
    int tid = threadIdx.x, lane = tid & 31, wid = tid >> 5;
    if (tid == 0) s_carry = 0;
    __syncthreads();
    for (int base = 0; base < NN; base += 4096) {
        int i0 = base + tid * 4;
        int v[4];
        #pragma unroll
        for (int u = 0; u < 4; u++) {
            int i = i0 + u;
            v[u] = (i < NN) ? g_cnt[i] : 0;
            if (i < NN) g_cnt[i] = 0;
        }
        int tsum = v[0] + v[1] + v[2] + v[3];
        int x = tsum;
        #pragma unroll
        for (int d = 1; d < 32; d <<= 1) {
            int t = __shfl_up_sync(0xffffffffu, x, d);
            if (lane >= d) x += t;
        }
        if (lane == 31) wsum[wid] = x;
        __syncthreads();
        if (wid == 0) {
            int w = wsum[lane];
            #pragma unroll
            for (int d = 1; d < 32; d <<= 1) {
                int t = __shfl_up_sync(0xffffffffu, w, d);
                if (lane >= d) w += t;
            }
            wsum[lane] = w;
        }
        __syncthreads();
        int carry = s_carry;
        int run = x - tsum + ((wid > 0) ? wsum[wid - 1] : 0) + carry;
        #pragma unroll
        for (int u = 0; u < 4; u++) {
            int i = i0 + u;
            if (i < NN) { g_off[i] = run; g_cur[i] = run; }
            run += v[u];
        }
        __syncthreads();
        if (tid == 0) s_carry = carry + wsum[31];
        __syncthreads();
    }
    if (tid == 0) g_off[NN] = s_carry;
}

// ---------------- scatter edges by dst ---------------------------------------
__global__ void k_scatter(const int* __restrict__ src, const int* __restrict__ dst,
                          const float4* __restrict__ ea) {
    int i = blockIdx.x * blockDim.x + threadIdx.x;
    if (i < EE) {
        int d = dst[i];
        int pos = atomicAdd(&g_cur[d], 1);
        g_srcp[pos] = src[i];
        float4* o = (float4*)g_eap;
        o[pos * 2]     = ea[i * 2];
        o[pos * 2 + 1] = ea[i * 2 + 1];
    }
}

// ------- fold ee@We into 8x64 per block: warp per output element ------------
__global__ void k_wc(const float* __restrict__ Wee, const float* __restrict__ bee,
                     const float* __restrict__ We, const float* __restrict__ be) {
    int lane = threadIdx.x & 31;
    int w = blockIdx.x * 8 + (threadIdx.x >> 5);
    if (w < 2048) {
        int b = w >> 9, k = (w >> 6) & 7, c = w & 63;
        float s = 0.f;
        for (int j = lane; j < 128; j += 32)
            s += Wee[k * 128 + j] * We[(b * 128 + j) * 64 + c];
        #pragma unroll
        for (int d = 16; d > 0; d >>= 1) s += __shfl_xor_sync(0xffffffffu, s, d);
        if (lane == 0) g_wc[w] = s;
    } else if (w < 2304) {
        int idx = w - 2048;
        int b = idx >> 6, c = idx & 63;
        float s = 0.f;
        for (int j = lane; j < 128; j += 32)
            s += bee[j] * We[(b * 128 + j) * 64 + c];
        #pragma unroll
        for (int d = 16; d > 0; d >>= 1) s += __shfl_xor_sync(0xffffffffu, s, d);
        if (lane == 0) g_bc[idx] = be[idx] + s;
    }
}

// ---------------- node encoder (+ fused LN/relu for block 0 -> bufA) --------
__global__ void k_encode(const float* __restrict__ x, const int* __restrict__ nidx,
                         const float* __restrict__ nodef,
                         const float* __restrict__ Woh, const float* __restrict__ boh,
                         const float* __restrict__ Wne, const float* __restrict__ bne,
                         const float* __restrict__ ln0g, const float* __restrict__ ln0b) {
    __shared__ float s_woh[64], s_boh[8], s_wne[2048], s_bne[128];
    for (int i = threadIdx.x; i < 64; i += blockDim.x) s_woh[i] = Woh[i];
    for (int i = threadIdx.x; i < 8; i += blockDim.x) s_boh[i] = boh[i];
    for (int i = threadIdx.x; i < 2048; i += blockDim.x) s_wne[i] = Wne[i];
    for (int i = threadIdx.x; i < 128; i += blockDim.x) s_bne[i] = bne[i];
    __syncthreads();
    int lane = threadIdx.x & 31;
    int warp = blockIdx.x * (blockDim.x >> 5) + (threadIdx.x >> 5);
    int nw = gridDim.x * (blockDim.x >> 5);
    for (int n = warp; n < NN; n += nw) {
        int s = nidx[n];
        float4 a  = *(const float4*)(nodef + s * 8);
        float4 b4 = *(const float4*)(nodef + s * 8 + 4);
        float nf1[8] = {a.x, a.y, a.z, a.w, b4.x, b4.y, b4.z, b4.w};
        float4 xa = *(const float4*)(x + n * 8);
        float4 xb = *(const float4*)(x + n * 8 + 4);
        float xv[8] = {xa.x, xa.y, xa.z, xa.w, xb.x, xb.y, xb.z, xb.w};
        float nf2[8];
        #pragma unroll
        for (int j = 0; j < 8; j++) {
            float t = s_boh[j];
            #pragma unroll
            for (int i = 0; i < 8; i++) t += xv[i] * s_woh[i * 8 + j];
            nf2[j] = t;
        }
        float acc[4];
        #pragma unroll
        for (int cc = 0; cc < 4; cc++) {
            int c = lane + cc * 32;
            float t = s_bne[c];
            #pragma unroll
            for (int k = 0; k < 8; k++) t += nf1[k] * s_wne[k * 128 + c];
            #pragma unroll
            for (int k = 0; k < 8; k++) t += nf2[k] * s_wne[(8 + k) * 128 + c];
            g_h[n * 128 + c] = t;
            acc[cc] = t;
        }
        float v0 = acc[2], v1 = acc[3];
        float su = v0 + v1, q = v0 * v0 + v1 * v1;
        #pragma unroll
        for (int d = 16; d > 0; d >>= 1) {
            su += __shfl_xor_sync(0xffffffffu, su, d);
            q  += __shfl_xor_sync(0xffffffffu, q, d);
        }
        float mu = su * (1.f / 64.f);
        float rs = rsqrtf(q * (1.f / 64.f) - mu * mu + 1e-5f);
        float r0 = fmaxf((v0 - mu) * rs * ln0g[lane] + ln0b[lane], 0.f);
        float r1 = fmaxf((v1 - mu) * rs * ln0g[lane + 32] + ln0b[lane + 32], 0.f);
        g_hblkA[n * 32 + lane] = make_float2(r0, r1);
    }
}

// per-edge message accumulate macro (unshifted softmax, exact algebra)
#define EDGE_STEP(e, hin, D0, D1, N0, N1)                                   \
    {                                                                        \
        int s_ = __ldg(&g_srcp[e]);                                          \
        float2 hv_ = __ldg(&hin[s_ * 32 + lane]);                            \
        float4 A_ = __ldg(&eap[(e) * 2]);                                    \
        float4 B_ = __ldg(&eap[(e) * 2 + 1]);                                \
        float t0_ = bc0 + hv_.x, t1_ = bc1 + hv_.y;                          \
        t0_ = fmaf(A_.x, wA[0], t0_);  t1_ = fmaf(A_.x, wB[0], t1_);         \
        t0_ = fmaf(A_.y, wA[1], t0_);  t1_ = fmaf(A_.y, wB[1], t1_);         \
        t0_ = fmaf(A_.z, wA[2], t0_);  t1_ = fmaf(A_.z, wB[2], t1_);         \
        t0_ = fmaf(A_.w, wA[3], t0_);  t1_ = fmaf(A_.w, wB[3], t1_);         \
        t0_ = fmaf(B_.x, wA[4], t0_);  t1_ = fmaf(B_.x, wB[4], t1_);         \
        t0_ = fmaf(B_.y, wA[5], t0_);  t1_ = fmaf(B_.y, wB[5], t1_);         \
        t0_ = fmaf(B_.z, wA[6], t0_);  t1_ = fmaf(B_.z, wB[6], t1_);         \
        t0_ = fmaf(B_.w, wA[7], t0_);  t1_ = fmaf(B_.w, wB[7], t1_);         \
        float v0_ = fmaxf(t0_, 0.f);                                         \
        float v1_ = fmaxf(t1_, 0.f);                                         \
        float ex0_ = __expf(v0_);                                            \
        float ex1_ = __expf(v1_);                                            \
        D0 += ex0_;  N0 = fmaf(v0_, ex0_, N0);                               \
        D1 += ex1_;  N1 = fmaf(v1_, ex1_, N1);                               \
    }

// ----- fused GEN block: 2 nodes per warp, interleaved edge streams ----------
// agg (unshifted softmax) + MLP + residual + next-block LN, ping-pong hblk.
__global__ void __launch_bounds__(256) k_aggmlp(
        int bsel, int rdsel, int outoff,
        const float* __restrict__ Wm, const float* __restrict__ bm,
        const float* __restrict__ ng, const float* __restrict__ nb) {
    __shared__ float wms[4096];
    for (int i = threadIdx.x; i < 4096; i += 256) wms[i] = Wm[bsel * 4096 + i];
    __syncthreads();
    const float2* __restrict__ hin = rdsel ? g_hblkB : g_hblkA;
    float2* __restrict__ hout = rdsel ? g_hblkA : g_hblkB;
    int lane = threadIdx.x & 31;
    int warp = blockIdx.x * 8 + (threadIdx.x >> 5);   // 6250*8*2 == NN exactly
    int nodeA = warp * 2, nodeB = nodeA + 1;
    const float* Wc = g_wc + bsel * 512;
    float wA[8], wB[8];
    #pragma unroll
    for (int k = 0; k < 8; k++) {
        wA[k] = __ldg(&Wc[k * 64 + lane]);
        wB[k] = __ldg(&Wc[k * 64 + lane + 32]);
    }
    float bc0 = __ldg(&g_bc[bsel * 64 + lane]);
    float bc1 = __ldg(&g_bc[bsel * 64 + lane + 32]);
    int eA0 = __ldg(&g_off[nodeA]);
    int eB0 = __ldg(&g_off[nodeB]);
    int eB1 = __ldg(&g_off[nodeB + 1]);
    int lenA = eB0 - eA0, lenB = eB1 - eB0;
    int lmin = min(lenA, lenB);
    float dA0 = 0.f, dA1 = 0.f, nA0 = 0.f, nA1 = 0.f;
    float dB0 = 0.f, dB1 = 0.f, nB0 = 0.f, nB1 = 0.f;
    const float4* eap = (const float4*)g_eap;
    // interleaved main loop: one edge of each node -> 2 independent chains
    for (int i = 0; i < lmin; i++) {
        EDGE_STEP(eA0 + i, hin, dA0, dA1, nA0, nA1);
        EDGE_STEP(eB0 + i, hin, dB0, dB1, nB0, nB1);
    }
    // remainders (warp-uniform branches)
    for (int i = lmin; i < lenA; i++) EDGE_STEP(eA0 + i, hin, dA0, dA1, nA0, nA1);
    for (int i = lmin; i < lenB; i++) EDGE_STEP(eB0 + i, hin, dB0, dB1, nB0, nB1);

    float2 hmeA = __ldg(&hin[nodeA * 32 + lane]);
    float2 hmeB = __ldg(&hin[nodeB * 32 + lane]);
    float aA0 = hmeA.x + ((lenA > 0) ? (nA0 / dA0 + 1e-7f) : 0.f);
    float aA1 = hmeA.y + ((lenA > 0) ? (nA1 / dA1 + 1e-7f) : 0.f);
    float aB0 = hmeB.x + ((lenB > 0) ? (nB0 / dB0 + 1e-7f) : 0.f);
    float aB1 = hmeB.y + ((lenB > 0) ? (nB1 / dB1 + 1e-7f) : 0.f);

    // MLP for both nodes, sharing each wms LDS load
    float b0 = __ldg(&bm[bsel * 64 + lane]);
    float b1 = __ldg(&bm[bsel * 64 + lane + 32]);
    float accA0 = b0, accA1 = b1, accB0 = b0, accB1 = b1;
    #pragma unroll
    for (int k = 0; k < 32; k++) {
        float w0 = wms[k * 64 + lane];
        float w1 = wms[k * 64 + lane + 32];
        float vA = __shfl_sync(0xffffffffu, aA0, k);
        float vB = __shfl_sync(0xffffffffu, aB0, k);
        accA0 = fmaf(vA, w0, accA0);  accA1 = fmaf(vA, w1, accA1);
        accB0 = fmaf(vB, w0, accB0);  accB1 = fmaf(vB, w1, accB1);
    }
    #pragma unroll
    for (int k = 0; k < 32; k++) {
        float w0 = wms[(k + 32) * 64 + lane];
        float w1 = wms[(k + 32) * 64 + lane + 32];
        float vA = __shfl_sync(0xffffffffu, aA1, k);
        float vB = __shfl_sync(0xffffffffu, aB1, k);
        accA0 = fmaf(vA, w0, accA0);  accA1 = fmaf(vA, w1, accA1);
        accB0 = fmaf(vB, w0, accB0);  accB1 = fmaf(vB, w1, accB1);
    }
    // residual add into g_h out-half
    float* oA = g_h + nodeA * 128 + outoff;
    float* oB = g_h + nodeB * 128 + outoff;
    float yA0 = oA[lane] + accA0, yA1 = oA[lane + 32] + accA1;
    float yB0 = oB[lane] + accB0, yB1 = oB[lane + 32] + accB1;
    oA[lane] = yA0;  oA[lane + 32] = yA1;
    oB[lane] = yB0;  oB[lane + 32] = yB1;
    // next block's LN+relu -> pong buffer
    if (ng) {
        float g0 = __ldg(&ng[lane]), g1 = __ldg(&ng[lane + 32]);
        float bb0 = __ldg(&nb[lane]), bb1 = __ldg(&nb[lane + 32]);
        float sA = yA0 + yA1, qA = yA0 * yA0 + yA1 * yA1;
        float sB = yB0 + yB1, qB = yB0 * yB0 + yB1 * yB1;
        #pragma unroll
        for (int d = 16; d > 0; d >>= 1) {
            sA += __shfl_xor_sync(0xffffffffu, sA, d);
            qA += __shfl_xor_sync(0xffffffffu, qA, d);
            sB += __shfl_xor_sync(0xffffffffu, sB, d);
            qB += __shfl_xor_sync(0xffffffffu, qB, d);
        }
        float muA = sA * (1.f / 64.f), muB = sB * (1.f / 64.f);
        float rsA = rsqrtf(qA * (1.f / 64.f) - muA * muA + 1e-5f);
        float rsB = rsqrtf(qB * (1.f / 64.f) - muB * muB + 1e-5f);
        hout[nodeA * 32 + lane] = make_float2(
            fmaxf((yA0 - muA) * rsA * g0 + bb0, 0.f),
            fmaxf((yA1 - muA) * rsA * g1 + bb1, 0.f));
        hout[nodeB * 32 + lane] = make_float2(
            fmaxf((yB0 - muB) * rsB * g0 + bb0, 0.f),
            fmaxf((yB1 - muB) * rsB * g1 + bb1, 0.f));
    }
}

// ---------------- final: out = relu(LN(h)) @ Wp + bp (56-col chunks) --------
__global__ void k_final(const float* __restrict__ lg, const float* __restrict__ lb,
                        const float* __restrict__ Wp, const float* __restrict__ bp,
                        float* __restrict__ out, int col0) {
    __shared__ float wps[128 * 56];
    for (int i = threadIdx.x; i < 128 * 56; i += blockDim.x) {
        int k = i / 56, c = i % 56;
        wps[i] = Wp[k * 112 + col0 + c];
    }
    __syncthreads();
    int lane = threadIdx.x & 31;
    int warp = blockIdx.x * (blockDim.x >> 5) + (threadIdx.x >> 5);
    int nw = gridDim.x * (blockDim.x >> 5);
    bool hasB = lane < 24;
    int cA = lane, cB = hasB ? lane + 32 : 0;
    float bpA = bp[col0 + cA];
    float bpB = hasB ? bp[col0 + lane + 32] : 0.f;
    float lgv[4], lbv[4];
    #pragma unroll
    for (int i = 0; i < 4; i++) { lgv[i] = lg[lane + i * 32]; lbv[i] = lb[lane + i * 32]; }
    for (int n = warp * 2; n < NN; n += nw * 2) {
        int n2 = n + 1;
        const float* hA = g_h + n * 128;
        const float* hB = g_h + n2 * 128;
        float xA[4], xB[4];
        #pragma unroll
        for (int i = 0; i < 4; i++) { xA[i] = hA[lane + i * 32]; xB[i] = hB[lane + i * 32]; }
        float sA = 0.f, qA = 0.f, sB = 0.f, qB = 0.f;
        #pragma unroll
        for (int i = 0; i < 4; i++) {
            sA += xA[i]; qA += xA[i] * xA[i];
            sB += xB[i]; qB += xB[i] * xB[i];
        }
        #pragma unroll
        for (int d = 16; d > 0; d >>= 1) {
            sA += __shfl_xor_sync(0xffffffffu, sA, d);
            qA += __shfl_xor_sync(0xffffffffu, qA, d);
            sB += __shfl_xor_sync(0xffffffffu, sB, d);
            qB += __shfl_xor_sync(0xffffffffu, qB, d);
        }
        float muA = sA * (1.f / 128.f), muB = sB * (1.f / 128.f);
        float rsA = rsqrtf(qA * (1.f / 128.f) - muA * muA + 1e-5f);
        float rsB = rsqrtf(qB * (1.f / 128.f) - muB * muB + 1e-5f);
        #pragma unroll
        for (int i = 0; i < 4; i++) {
            xA[i] = fmaxf((xA[i] - muA) * rsA * lgv[i] + lbv[i], 0.f);
            xB[i] = fmaxf((xB[i] - muB) * rsB * lgv[i] + lbv[i], 0.f);
        }
        float aA0 = bpA, aA1 = bpB, aB0 = bpA, aB1 = bpB;
        #pragma unroll
        for (int i = 0; i < 4; i++) {
            #pragma unroll
            for (int k = 0; k < 32; k++) {
                float w0 = wps[(k + i * 32) * 56 + cA];
                float w1 = wps[(k + i * 32) * 56 + cB];
                float vA = __shfl_sync(0xffffffffu, xA[i], k);
                float vB = __shfl_sync(0xffffffffu, xB[i], k);
                aA0 = fmaf(vA, w0, aA0);  aA1 = fmaf(vA, w1, aA1);
                aB0 = fmaf(vB, w0, aB0);  aB1 = fmaf(vB, w1, aB1);
            }
        }
        out[n * 112 + col0 + cA] = aA0;
        out[n2 * 112 + col0 + cA] = aB0;
        if (hasB) {
            out[n * 112 + col0 + lane + 32] = aA1;
            out[n2 * 112 + col0 + lane + 32] = aB1;
        }
    }
}

// ---------------- launch ----------------------------------------------------
extern "C" void kernel_launch(void* const* d_in, const int* in_sizes, int n_in,
                              void* d_out, int out_size) {
    const float* x     = (const float*)d_in[0];
    const int*   nidx  = (const int*)d_in[1];
    const int*   ei    = (const int*)d_in[2];
    const float* ea    = (const float*)d_in[3];
    const float* nodef = (const float*)d_in[4];
    const float* Woh   = (const float*)d_in[5];
    const float* boh   = (const float*)d_in[6];
    const float* Wne   = (const float*)d_in[7];
    const float* bne   = (const float*)d_in[8];
    const float* Wee   = (const float*)d_in[9];
    const float* bee   = (const float*)d_in[10];
    const float* lng   = (const float*)d_in[11];
    const float* lnb   = (const float*)d_in[12];
    const float* We    = (const float*)d_in[13];
    const float* be    = (const float*)d_in[14];
    const float* Wm    = (const float*)d_in[15];
    const float* bm    = (const float*)d_in[16];
    const float* lastg = (const float*)d_in[17];
    const float* lastb = (const float*)d_in[18];
    const float* Wp    = (const float*)d_in[19];
    const float* bp    = (const float*)d_in[20];
    float* out = (float*)d_out;

    const int* src = ei;
    const int* dst = ei + EE;

    k_hist<<<(EE + 255) / 256, 256>>>(dst);
    k_scan<<<1, 1024>>>();
    k_scatter<<<(EE + 255) / 256, 256>>>(src, dst, (const float4*)ea);
    k_wc<<<288, 256>>>(Wee, bee, We, be);
    k_encode<<<1184, 256>>>(x, nidx, nodef, Woh, boh, Wne, bne, lng, lnb);

    for (int b = 0; b < 4; b++) {
        int outoff = (b & 1) ? 64 : 0;
        const float* ng = (b < 3) ? (lng + (b + 1) * 64) : (const float*)0;
        const float* nbp = (b < 3) ? (lnb + (b + 1) * 64) : (const float*)0;
        k_aggmlp<<<NN / 16, 256>>>(b, b & 1, outoff, Wm, bm, ng, nbp);
    }

    k_final<<<1184, 256>>>(lastg, lastb, Wp, bp, out, 0);
    k_final<<<1184, 256>>>(lastg, lastb, Wp, bp, out, 56);
}